// round 13
// baseline (speedup 1.0000x reference)
#include <cuda_runtime.h>
#include <cuda_bf16.h>
#include <math.h>
#include <stdint.h>

#define DIM   768
#define MAXN  10000
#define MAXE  100000

// ---------------- scratch (static device globals; no allocation) ----------------
__device__ float g_h [MAXN * DIM];     // h = x @ W (per-layer, reused)
__device__ float g_as1[MAXN], g_ad1[MAXN];
__device__ float g_as2[MAXN], g_ad2[MAXN];
__device__ int   g_cnt[MAXN];
__device__ int   g_rowptr[MAXN + 1];
__device__ int   g_cursor[MAXN];
__device__ int   g_srcs[MAXE + MAXN];
// bf16 split operands
__device__ __nv_bfloat16 g_ah[MAXN * DIM];
__device__ __nv_bfloat16 g_al[MAXN * DIM];
__device__ __nv_bfloat16 g_w1h[DIM * DIM], g_w1l[DIM * DIM];   // W1^T split
__device__ __nv_bfloat16 g_w2h[DIM * DIM], g_w2l[DIM * DIM];   // W2^T split

// ---------------- mma.sync helpers (sm_80+ path; valid on plain sm_103) ------
__device__ __forceinline__ void mma_bf16(float* c, const uint32_t* a, const uint32_t* b) {
    asm volatile(
        "mma.sync.aligned.m16n8k16.row.col.f32.bf16.bf16.f32 "
        "{%0,%1,%2,%3}, {%4,%5,%6,%7}, {%8,%9}, {%0,%1,%2,%3};"
        : "+f"(c[0]), "+f"(c[1]), "+f"(c[2]), "+f"(c[3])
        : "r"(a[0]), "r"(a[1]), "r"(a[2]), "r"(a[3]), "r"(b[0]), "r"(b[1]));
}
__device__ __forceinline__ void ldm4(uint32_t* r, uint32_t addr) {
    asm volatile("ldmatrix.sync.aligned.m8n8.x4.shared.b16 {%0,%1,%2,%3}, [%4];"
                 : "=r"(r[0]), "=r"(r[1]), "=r"(r[2]), "=r"(r[3]) : "r"(addr));
}
__device__ __forceinline__ void cpa16(uint32_t dst, const void* src, int src_bytes) {
    asm volatile("cp.async.ca.shared.global [%0], [%1], 16, %2;"
                 :: "r"(dst), "l"(src), "r"(src_bytes));
}
__device__ __forceinline__ void cpa_commit() {
    asm volatile("cp.async.commit_group;" ::: "memory");
}
template <int N>
__device__ __forceinline__ void cpa_wait() {
    asm volatile("cp.async.wait_group %0;" :: "n"(N) : "memory");
}

// ---------------- tensor-core GEMM + fused attention dots ----------------
// C = Ah*Bh + Ah*Bl + Al*Bh (fp32 accum). CTA tile 128x256, BK=32.
// 256 threads, 8 warps (2x4), warp tile 64x64. 3-stage cp.async pipeline.
// Epilogue also accumulates as_[m] += C[m,:].att_s, ad_[m] += C[m,:].att_d.
#define BM       128
#define BN       256
#define SM_AH    0
#define SM_AL    10240                 // 128 rows * 80 B
#define SM_BH    20480
#define SM_BL    40960                 // 256 rows * 80 B
#define SM_STAGE 61440
#define SM_TOT   (SM_STAGE * 3)        // 184320 B

__global__ __launch_bounds__(256, 1) void gemm_mma(
        int M,
        const __nv_bfloat16* __restrict__ Ah, const __nv_bfloat16* __restrict__ Al,
        const __nv_bfloat16* __restrict__ Bh, const __nv_bfloat16* __restrict__ Bl,
        const float* __restrict__ att_s, const float* __restrict__ att_d,
        float* __restrict__ as_, float* __restrict__ ad_,
        float* __restrict__ C) {
    extern __shared__ char dsm[];
    const uint32_t sb = (uint32_t)__cvta_generic_to_shared(dsm);

    const int tid  = threadIdx.x;
    const int lane = tid & 31;
    const int warp = tid >> 5;           // 0..7
    const int wm   = warp >> 2;          // 0..1  (64 rows each)
    const int wn   = warp & 3;           // 0..3  (64 cols each)
    const int m0   = blockIdx.y * BM;
    const int n0   = blockIdx.x * BN;
    const int rowsv = min(BM, M - m0);

    float acc[4][8][4];                  // mt, nt(8 cols of 8), frag
#pragma unroll
    for (int i = 0; i < 4; i++)
#pragma unroll
        for (int j = 0; j < 8; j++)
#pragma unroll
            for (int q = 0; q < 4; q++) acc[i][j][q] = 0.f;

    const int amat = lane >> 3, ar = lane & 7;
    const int a_row_off = ((amat & 1) << 3) + ar;
    const int a_col_off = (amat >> 1) << 3;
    const int b_row_off = ((amat >> 1) << 3) + ar;
    const int b_col_off = (amat & 1) << 3;

    const int NT = DIM / 32;

    // stage one 32-K chunk: A 512 16B-chunks x2 arrays, B 1024 x2 arrays
    auto stage = [&](int s, int k0) {
        const uint32_t base = sb + s * SM_STAGE;
#pragma unroll
        for (int i = tid; i < 512; i += 256) {
            const int row = i >> 2, chk = i & 3;
            const uint32_t so = (uint32_t)(row * 80 + chk * 16);
            const bool av = row < rowsv;
            const size_t ga = (size_t)(m0 + (av ? row : 0)) * DIM + k0 + chk * 8;
            const int asz = av ? 16 : 0;
            cpa16(base + SM_AH + so, Ah + ga, asz);
            cpa16(base + SM_AL + so, Al + ga, asz);
        }
#pragma unroll
        for (int i = tid; i < 1024; i += 256) {
            const int row = i >> 2, chk = i & 3;
            const uint32_t so = (uint32_t)(row * 80 + chk * 16);
            const size_t gb = (size_t)(n0 + row) * DIM + k0 + chk * 8;
            cpa16(base + SM_BH + so, Bh + gb, 16);
            cpa16(base + SM_BL + so, Bl + gb, 16);
        }
    };

    stage(0, 0);  cpa_commit();
    stage(1, 32); cpa_commit();

    for (int it = 0; it < NT; it++) {
        cpa_wait<1>();            // buffer it%3's group complete
        __syncthreads();          // prev readers of (it+2)%3 done
        if (it + 2 < NT) { stage((it + 2) % 3, (it + 2) * 32); cpa_commit(); }

        const uint32_t bA = sb + (it % 3) * SM_STAGE;
#pragma unroll
        for (int kc = 0; kc < 2; kc++) {
            uint32_t ah[4][4], al[4][4];
#pragma unroll
            for (int mt = 0; mt < 4; mt++) {
                const uint32_t off =
                    (uint32_t)((wm * 64 + mt * 16 + a_row_off) * 80 +
                               (kc * 16 + a_col_off) * 2);
                ldm4(ah[mt], bA + SM_AH + off);
                ldm4(al[mt], bA + SM_AL + off);
            }
#pragma unroll
            for (int p = 0; p < 4; p++) {    // 16-col group within warp's 64
                uint32_t bh4[4], bl4[4];
                const uint32_t off =
                    (uint32_t)((wn * 64 + p * 16 + b_row_off) * 80 +
                               (kc * 16 + b_col_off) * 2);
                ldm4(bh4, bA + SM_BH + off);
                ldm4(bl4, bA + SM_BL + off);
#pragma unroll
                for (int mt = 0; mt < 4; mt++)
#pragma unroll
                    for (int q = 0; q < 2; q++)
                        mma_bf16(acc[mt][p * 2 + q], ah[mt], &bh4[q * 2]);
#pragma unroll
                for (int mt = 0; mt < 4; mt++)
#pragma unroll
                    for (int q = 0; q < 2; q++)
                        mma_bf16(acc[mt][p * 2 + q], ah[mt], &bl4[q * 2]);
#pragma unroll
                for (int mt = 0; mt < 4; mt++)
#pragma unroll
                    for (int q = 0; q < 2; q++)
                        mma_bf16(acc[mt][p * 2 + q], al[mt], &bh4[q * 2]);
            }
        }
    }
    __syncthreads();

    // ---- epilogue: store C + fused attention dot partials ----
    const int gr = lane >> 2, gc = (lane & 3) * 2;
#pragma unroll
    for (int mt = 0; mt < 4; mt++) {
        float s0 = 0.f, s1 = 0.f, d0 = 0.f, d1 = 0.f;
#pragma unroll
        for (int nt = 0; nt < 8; nt++) {
            const int m = m0 + wm * 64 + mt * 16 + gr;
            const int n = n0 + wn * 64 + nt * 8 + gc;
            const float2 av = *reinterpret_cast<const float2*>(att_s + n);
            const float2 dv = *reinterpret_cast<const float2*>(att_d + n);
            s0 += acc[mt][nt][0] * av.x + acc[mt][nt][1] * av.y;
            s1 += acc[mt][nt][2] * av.x + acc[mt][nt][3] * av.y;
            d0 += acc[mt][nt][0] * dv.x + acc[mt][nt][1] * dv.y;
            d1 += acc[mt][nt][2] * dv.x + acc[mt][nt][3] * dv.y;
            if (m < M)
                *reinterpret_cast<float2*>(&C[(size_t)m * DIM + n]) =
                    make_float2(acc[mt][nt][0], acc[mt][nt][1]);
            if (m + 8 < M)
                *reinterpret_cast<float2*>(&C[(size_t)(m + 8) * DIM + n]) =
                    make_float2(acc[mt][nt][2], acc[mt][nt][3]);
        }
#pragma unroll
        for (int o = 1; o < 4; o <<= 1) {
            s0 += __shfl_xor_sync(0xffffffffu, s0, o);
            s1 += __shfl_xor_sync(0xffffffffu, s1, o);
            d0 += __shfl_xor_sync(0xffffffffu, d0, o);
            d1 += __shfl_xor_sync(0xffffffffu, d1, o);
        }
        if ((lane & 3) == 0) {
            const int m = m0 + wm * 64 + mt * 16 + gr;
            if (m < M)     { atomicAdd(&as_[m], s0);     atomicAdd(&ad_[m], d0); }
            if (m + 8 < M) { atomicAdd(&as_[m + 8], s1); atomicAdd(&ad_[m + 8], d1); }
        }
    }
}

// ---------------- bf16 split conversions ----------------
__global__ void split_x(const float* __restrict__ x, __nv_bfloat16* __restrict__ hi,
                        __nv_bfloat16* __restrict__ lo, int total) {
    const int i = blockIdx.x * blockDim.x + threadIdx.x;
    if (i >= total) return;
    const float v = x[i];
    const __nv_bfloat16 h = __float2bfloat16(v);
    hi[i] = h;
    lo[i] = __float2bfloat16(v - __bfloat162float(h));
}

// batched: z=0 -> W1, z=1 -> W2.  W [K][N] row-major -> Wt hi/lo [N][K]
__global__ void split_wT(const float* __restrict__ Wa, const float* __restrict__ Wb,
                         __nv_bfloat16* __restrict__ hA, __nv_bfloat16* __restrict__ lA,
                         __nv_bfloat16* __restrict__ hB, __nv_bfloat16* __restrict__ lB) {
    const float* W = blockIdx.z ? Wb : Wa;
    __nv_bfloat16* hiT = blockIdx.z ? hB : hA;
    __nv_bfloat16* loT = blockIdx.z ? lB : lA;
    __shared__ float t[32][33];
    const int bx = blockIdx.x * 32, by = blockIdx.y * 32;
    const int tx = threadIdx.x, ty = threadIdx.y;
    #pragma unroll
    for (int j = 0; j < 4; j++)
        t[ty + j * 8][tx] = W[(size_t)(by + ty + j * 8) * DIM + bx + tx];
    __syncthreads();
    #pragma unroll
    for (int j = 0; j < 4; j++) {
        const float v = t[tx][ty + j * 8];
        const __nv_bfloat16 h = __float2bfloat16(v);
        const size_t o = (size_t)(bx + ty + j * 8) * DIM + by + tx;
        hiT[o] = h;
        loT[o] = __float2bfloat16(v - __bfloat162float(h));
    }
}

// zero cnt + both layers' attention accumulators in one launch
__global__ void zero_all(int* __restrict__ cnt,
                         float* __restrict__ a1, float* __restrict__ d1,
                         float* __restrict__ a2, float* __restrict__ d2, int n) {
    const int i = blockIdx.x * blockDim.x + threadIdx.x;
    if (i < n) { cnt[i] = 0; a1[i] = 0.f; d1[i] = 0.f; a2[i] = 0.f; d2[i] = 0.f; }
}

// ---------------- CSR build ----------------
__global__ void hist_k(const int* __restrict__ ei, int nE, int nN, int* __restrict__ cnt) {
    const int e = blockIdx.x * blockDim.x + threadIdx.x;
    if (e >= nE + nN) return;
    const int d = (e < nE) ? ei[nE + e] : (e - nE);
    atomicAdd(&cnt[d], 1);
}
__global__ void scan_rowptr(const int* __restrict__ cnt, int* __restrict__ rowptr,
                            int* __restrict__ cursor, int n) {
    __shared__ int sh[32];
    __shared__ int carry_sh;
    const int tid = threadIdx.x, lane = tid & 31, wid = tid >> 5;
    if (tid == 0) carry_sh = 0;
    __syncthreads();
    for (int base = 0; base < n; base += 1024) {
        const int i = base + tid;
        const int v = (i < n) ? cnt[i] : 0;
        int x = v;
#pragma unroll
        for (int o = 1; o < 32; o <<= 1) {
            int y = __shfl_up_sync(0xffffffffu, x, o);
            if (lane >= o) x += y;
        }
        if (lane == 31) sh[wid] = x;
        __syncthreads();
        if (wid == 0) {
            int s = sh[lane];
#pragma unroll
            for (int o = 1; o < 32; o <<= 1) {
                int y = __shfl_up_sync(0xffffffffu, s, o);
                if (lane >= o) s += y;
            }
            sh[lane] = s;
        }
        __syncthreads();
        const int incl = x + (wid > 0 ? sh[wid - 1] : 0);
        const int carry = carry_sh;
        if (i < n) { rowptr[i] = carry + incl - v; cursor[i] = carry + incl - v; }
        __syncthreads();
        if (tid == 1023) carry_sh = carry + incl;
        __syncthreads();
    }
    if (threadIdx.x == 0) rowptr[n] = carry_sh;
}
__global__ void fill_csr(const int* __restrict__ ei, int nE, int nN,
                         int* __restrict__ cursor, int* __restrict__ srcs) {
    const int e = blockIdx.x * blockDim.x + threadIdx.x;
    if (e >= nE + nN) return;
    int s, d;
    if (e < nE) { s = ei[e]; d = ei[nE + e]; }
    else        { s = d = e - nE; }
    const int pos = atomicAdd(&cursor[d], 1);
    srcs[pos] = s;
}

// ---------------- fused per-node softmax + gather ----------------
// mode 0: write float out (layer 2, no relu)
// mode 1: relu, then write bf16 hi/lo split (layer 1 -> layer 2 GEMM operands)
__global__ void gat_gather(const int* __restrict__ rowptr, const int* __restrict__ srcs,
                           const float* __restrict__ as_, const float* __restrict__ ad_,
                           const float* __restrict__ h, const float* __restrict__ bias,
                           float* __restrict__ outF,
                           __nv_bfloat16* __restrict__ outH,
                           __nv_bfloat16* __restrict__ outL,
                           int n, int mode) {
    const int node = blockIdx.x * (blockDim.x >> 5) + (threadIdx.x >> 5);
    const int lane = threadIdx.x & 31;
    if (node >= n) return;
    const int beg = rowptr[node], end = rowptr[node + 1];
    const float adn = ad_[node];

    float mx = -INFINITY;
    for (int j = beg + lane; j < end; j += 32) {
        float v = as_[srcs[j]] + adn;
        v = v > 0.f ? v : 0.2f * v;
        mx = fmaxf(mx, v);
    }
#pragma unroll
    for (int o = 16; o; o >>= 1) mx = fmaxf(mx, __shfl_xor_sync(0xffffffffu, mx, o));

    float den = 0.f;
    for (int j = beg + lane; j < end; j += 32) {
        float v = as_[srcs[j]] + adn;
        v = v > 0.f ? v : 0.2f * v;
        den += expf(v - mx);
    }
#pragma unroll
    for (int o = 16; o; o >>= 1) den += __shfl_xor_sync(0xffffffffu, den, o);
    const float inv = 1.f / den;

    float4 acc[DIM / 128];
#pragma unroll
    for (int q = 0; q < DIM / 128; q++) acc[q] = make_float4(0.f, 0.f, 0.f, 0.f);

    for (int j0 = beg; j0 < end; j0 += 32) {
        const int j = j0 + lane;
        float w = 0.f; int s = 0;
        if (j < end) {
            s = srcs[j];
            float v = as_[s] + adn;
            v = v > 0.f ? v : 0.2f * v;
            w = expf(v - mx) * inv;
        }
        const int cnt = min(32, end - j0);
        for (int t = 0; t < cnt; t++) {
            const float wt = __shfl_sync(0xffffffffu, w, t);
            const int   st = __shfl_sync(0xffffffffu, s, t);
            const float4* hr = reinterpret_cast<const float4*>(h + (size_t)st * DIM);
#pragma unroll
            for (int q = 0; q < DIM / 128; q++) {
                const float4 v = hr[lane + 32 * q];
                acc[q].x += wt * v.x; acc[q].y += wt * v.y;
                acc[q].z += wt * v.z; acc[q].w += wt * v.w;
            }
        }
    }

    const float4* b4 = reinterpret_cast<const float4*>(bias);
#pragma unroll
    for (int q = 0; q < DIM / 128; q++) {
        const float4 bv = b4[lane + 32 * q];
        float4 r = make_float4(acc[q].x + bv.x, acc[q].y + bv.y,
                               acc[q].z + bv.z, acc[q].w + bv.w);
        if (mode == 1) {
            r.x = fmaxf(r.x, 0.f); r.y = fmaxf(r.y, 0.f);
            r.z = fmaxf(r.z, 0.f); r.w = fmaxf(r.w, 0.f);
            const size_t off = (size_t)node * DIM + (lane + 32 * q) * 4;
            float hx = __bfloat162float(__float2bfloat16(r.x));
            float hy = __bfloat162float(__float2bfloat16(r.y));
            float hz = __bfloat162float(__float2bfloat16(r.z));
            float hw = __bfloat162float(__float2bfloat16(r.w));
            __nv_bfloat162 h01, h23, l01, l23;
            h01 = __nv_bfloat162(__float2bfloat16(r.x), __float2bfloat16(r.y));
            h23 = __nv_bfloat162(__float2bfloat16(r.z), __float2bfloat16(r.w));
            l01 = __nv_bfloat162(__float2bfloat16(r.x - hx), __float2bfloat16(r.y - hy));
            l23 = __nv_bfloat162(__float2bfloat16(r.z - hz), __float2bfloat16(r.w - hw));
            uint2 hp = make_uint2(*(uint32_t*)&h01, *(uint32_t*)&h23);
            uint2 lp = make_uint2(*(uint32_t*)&l01, *(uint32_t*)&l23);
            *reinterpret_cast<uint2*>(outH + off) = hp;
            *reinterpret_cast<uint2*>(outL + off) = lp;
        } else {
            float4* o4 = reinterpret_cast<float4*>(outF + (size_t)node * DIM);
            o4[lane + 32 * q] = r;
        }
    }
}

// ---------------- launch ----------------
extern "C" void kernel_launch(void* const* d_in, const int* in_sizes, int n_in,
                              void* d_out, int out_size) {
    const float* x    = (const float*)d_in[0];
    const int*   ei   = (const int*)d_in[1];     // int32 edge_index [2, E]
    const float* W1   = (const float*)d_in[2];
    const float* as1  = (const float*)d_in[3];
    const float* ad1  = (const float*)d_in[4];
    const float* b1   = (const float*)d_in[5];
    const float* W2   = (const float*)d_in[6];
    const float* as2  = (const float*)d_in[7];
    const float* ad2  = (const float*)d_in[8];
    const float* b2   = (const float*)d_in[9];

    const int n_nodes = in_sizes[0] / DIM;
    const int n_edges = in_sizes[1] / 2;
    const int tot     = n_edges + n_nodes;

    float *h, *asL1, *adL1, *asL2, *adL2;
    int *cnt, *rowptr, *cursor, *srcs;
    __nv_bfloat16 *ah, *al, *w1h, *w1l, *w2h, *w2l;
    cudaGetSymbolAddress((void**)&h,      g_h);
    cudaGetSymbolAddress((void**)&asL1,   g_as1);
    cudaGetSymbolAddress((void**)&adL1,   g_ad1);
    cudaGetSymbolAddress((void**)&asL2,   g_as2);
    cudaGetSymbolAddress((void**)&adL2,   g_ad2);
    cudaGetSymbolAddress((void**)&cnt,    g_cnt);
    cudaGetSymbolAddress((void**)&rowptr, g_rowptr);
    cudaGetSymbolAddress((void**)&cursor, g_cursor);
    cudaGetSymbolAddress((void**)&srcs,   g_srcs);
    cudaGetSymbolAddress((void**)&ah,     g_ah);
    cudaGetSymbolAddress((void**)&al,     g_al);
    cudaGetSymbolAddress((void**)&w1h,    g_w1h);
    cudaGetSymbolAddress((void**)&w1l,    g_w1l);
    cudaGetSymbolAddress((void**)&w2h,    g_w2h);
    cudaGetSymbolAddress((void**)&w2l,    g_w2l);

    cudaFuncSetAttribute(gemm_mma, cudaFuncAttributeMaxDynamicSharedMemorySize, SM_TOT);

    const int nd_total = n_nodes * DIM;
    const dim3 gemm_grid(DIM / BN, (n_nodes + BM - 1) / BM);
    const dim3 tr_grid(DIM / 32, DIM / 32, 2), tr_blk(32, 8);

    // 0: zero everything (cnt + both layers' attention accumulators)
    zero_all<<<(n_nodes + 255) / 256, 256>>>(cnt, asL1, adL1, asL2, adL2, n_nodes);
    // 1: both weight splits (batched)
    split_wT<<<tr_grid, tr_blk>>>(W1, W2, w1h, w1l, w2h, w2l);
    // 2: layer-1 input split
    split_x<<<(nd_total + 255) / 256, 256>>>(x, ah, al, nd_total);
    // 3: layer-1 GEMM  <-- ncu capture slot
    gemm_mma<<<gemm_grid, 256, SM_TOT>>>(n_nodes, ah, al, w1h, w1l,
                                         as1, ad1, asL1, adL1, h);
    // 4-6: CSR build (only needed by gather)
    hist_k<<<(tot + 255) / 256, 256>>>(ei, n_edges, n_nodes, cnt);
    scan_rowptr<<<1, 1024>>>(cnt, rowptr, cursor, n_nodes);
    fill_csr<<<(tot + 255) / 256, 256>>>(ei, n_edges, n_nodes, cursor, srcs);
    // 7: layer-1 gather (writes bf16 split for layer 2)
    gat_gather<<<(n_nodes + 7) / 8, 256>>>(rowptr, srcs, asL1, adL1, h, b1,
                                           nullptr, ah, al, n_nodes, 1);
    // 8: layer-2 GEMM
    gemm_mma<<<gemm_grid, 256, SM_TOT>>>(n_nodes, ah, al, w2h, w2l,
                                         as2, ad2, asL2, adL2, h);
    // 9: layer-2 gather -> output
    gat_gather<<<(n_nodes + 7) / 8, 256>>>(rowptr, srcs, asL2, adL2, h, b2,
                                           (float*)d_out, nullptr, nullptr, n_nodes, 0);
}

// round 14
// speedup vs baseline: 1.3016x; 1.3016x over previous
#include <cuda_runtime.h>
#include <cuda_fp16.h>
#include <math.h>
#include <stdint.h>

#define DIM   768
#define MAXN  10000
#define MAXE  100000

// ---------------- scratch (static device globals; no allocation) ----------------
__device__ float g_h [MAXN * DIM];     // h = x @ W (per-layer, reused)
__device__ float g_as1[MAXN], g_ad1[MAXN];
__device__ float g_as2[MAXN], g_ad2[MAXN];
__device__ int   g_cnt[MAXN];
__device__ int   g_rowptr[MAXN + 1];
__device__ int   g_cursor[MAXN];
__device__ int   g_srcs[MAXE + MAXN];
// fp16 split operands: A = Ah + Al (exact to ~2^-24); B = Bh (fp16, ~2^-12)
__device__ __half g_ah[MAXN * DIM];
__device__ __half g_al[MAXN * DIM];
__device__ __half g_w1h[DIM * DIM];    // W1^T fp16
__device__ __half g_w2h[DIM * DIM];    // W2^T fp16

// ---------------- mma.sync helpers (sm_80+ path; valid on plain sm_103) ------
__device__ __forceinline__ void mma_f16(float* c, const uint32_t* a, const uint32_t* b) {
    asm volatile(
        "mma.sync.aligned.m16n8k16.row.col.f32.f16.f16.f32 "
        "{%0,%1,%2,%3}, {%4,%5,%6,%7}, {%8,%9}, {%0,%1,%2,%3};"
        : "+f"(c[0]), "+f"(c[1]), "+f"(c[2]), "+f"(c[3])
        : "r"(a[0]), "r"(a[1]), "r"(a[2]), "r"(a[3]), "r"(b[0]), "r"(b[1]));
}
__device__ __forceinline__ void ldm4(uint32_t* r, uint32_t addr) {
    asm volatile("ldmatrix.sync.aligned.m8n8.x4.shared.b16 {%0,%1,%2,%3}, [%4];"
                 : "=r"(r[0]), "=r"(r[1]), "=r"(r[2]), "=r"(r[3]) : "r"(addr));
}
__device__ __forceinline__ void cpa16(uint32_t dst, const void* src, int src_bytes) {
    asm volatile("cp.async.ca.shared.global [%0], [%1], 16, %2;"
                 :: "r"(dst), "l"(src), "r"(src_bytes));
}
__device__ __forceinline__ void cpa_commit() {
    asm volatile("cp.async.commit_group;" ::: "memory");
}
template <int N>
__device__ __forceinline__ void cpa_wait() {
    asm volatile("cp.async.wait_group %0;" :: "n"(N) : "memory");
}

// ---------------- tensor-core GEMM + fused attention dots ----------------
// C = Ah*Bh + Al*Bh (fp32 accum). CTA tile 128x256, BK=32.
// 256 threads, 8 warps (2x4), warp tile 64x64. 3-stage cp.async pipeline.
// Staged arrays per iter: Ah, Al (128 rows) + Bh (256 rows) = 2048 cp.async.
#define BM       128
#define BN       256
#define SM_AH    0
#define SM_AL    10240                 // 128 rows * 80 B
#define SM_BH    20480                 // 256 rows * 80 B
#define SM_STAGE 40960
#define SM_TOT   (SM_STAGE * 3)        // 122880 B

__global__ __launch_bounds__(256, 1) void gemm_mma(
        int M,
        const __half* __restrict__ Ah, const __half* __restrict__ Al,
        const __half* __restrict__ Bh,
        const float* __restrict__ att_s, const float* __restrict__ att_d,
        float* __restrict__ as_, float* __restrict__ ad_,
        float* __restrict__ C) {
    extern __shared__ char dsm[];
    const uint32_t sb = (uint32_t)__cvta_generic_to_shared(dsm);

    const int tid  = threadIdx.x;
    const int lane = tid & 31;
    const int warp = tid >> 5;           // 0..7
    const int wm   = warp >> 2;          // 0..1  (64 rows each)
    const int wn   = warp & 3;           // 0..3  (64 cols each)
    const int m0   = blockIdx.y * BM;
    const int n0   = blockIdx.x * BN;
    const int rowsv = min(BM, M - m0);

    float acc[4][8][4];                  // mt, nt(8 cols of 8), frag
#pragma unroll
    for (int i = 0; i < 4; i++)
#pragma unroll
        for (int j = 0; j < 8; j++)
#pragma unroll
            for (int q = 0; q < 4; q++) acc[i][j][q] = 0.f;

    const int amat = lane >> 3, ar = lane & 7;
    const int a_row_off = ((amat & 1) << 3) + ar;
    const int a_col_off = (amat >> 1) << 3;
    const int b_row_off = ((amat >> 1) << 3) + ar;
    const int b_col_off = (amat & 1) << 3;

    const int NT = DIM / 32;

    // stage one 32-K chunk: A 512 16B-chunks x2 arrays, B 1024 x1 array
    auto stage = [&](int s, int k0) {
        const uint32_t base = sb + s * SM_STAGE;
#pragma unroll
        for (int i = tid; i < 512; i += 256) {
            const int row = i >> 2, chk = i & 3;
            const uint32_t so = (uint32_t)(row * 80 + chk * 16);
            const bool av = row < rowsv;
            const size_t ga = (size_t)(m0 + (av ? row : 0)) * DIM + k0 + chk * 8;
            const int asz = av ? 16 : 0;
            cpa16(base + SM_AH + so, Ah + ga, asz);
            cpa16(base + SM_AL + so, Al + ga, asz);
        }
#pragma unroll
        for (int i = tid; i < 1024; i += 256) {
            const int row = i >> 2, chk = i & 3;
            const uint32_t so = (uint32_t)(row * 80 + chk * 16);
            const size_t gb = (size_t)(n0 + row) * DIM + k0 + chk * 8;
            cpa16(base + SM_BH + so, Bh + gb, 16);
        }
    };

    stage(0, 0);  cpa_commit();
    stage(1, 32); cpa_commit();

    for (int it = 0; it < NT; it++) {
        cpa_wait<1>();            // buffer it%3's group complete
        __syncthreads();          // prev readers of (it+2)%3 done
        if (it + 2 < NT) { stage((it + 2) % 3, (it + 2) * 32); cpa_commit(); }

        const uint32_t bA = sb + (it % 3) * SM_STAGE;
#pragma unroll
        for (int kc = 0; kc < 2; kc++) {
            uint32_t ah[4][4], al[4][4];
#pragma unroll
            for (int mt = 0; mt < 4; mt++) {
                const uint32_t off =
                    (uint32_t)((wm * 64 + mt * 16 + a_row_off) * 80 +
                               (kc * 16 + a_col_off) * 2);
                ldm4(ah[mt], bA + SM_AH + off);
                ldm4(al[mt], bA + SM_AL + off);
            }
#pragma unroll
            for (int p = 0; p < 4; p++) {    // 16-col group within warp's 64
                uint32_t bh4[4];
                const uint32_t off =
                    (uint32_t)((wn * 64 + p * 16 + b_row_off) * 80 +
                               (kc * 16 + b_col_off) * 2);
                ldm4(bh4, bA + SM_BH + off);
#pragma unroll
                for (int mt = 0; mt < 4; mt++)
#pragma unroll
                    for (int q = 0; q < 2; q++)
                        mma_f16(acc[mt][p * 2 + q], ah[mt], &bh4[q * 2]);
#pragma unroll
                for (int mt = 0; mt < 4; mt++)
#pragma unroll
                    for (int q = 0; q < 2; q++)
                        mma_f16(acc[mt][p * 2 + q], al[mt], &bh4[q * 2]);
            }
        }
    }
    __syncthreads();

    // ---- epilogue: store C + fused attention dot partials ----
    const int gr = lane >> 2, gc = (lane & 3) * 2;
#pragma unroll
    for (int mt = 0; mt < 4; mt++) {
        float s0 = 0.f, s1 = 0.f, d0 = 0.f, d1 = 0.f;
#pragma unroll
        for (int nt = 0; nt < 8; nt++) {
            const int m = m0 + wm * 64 + mt * 16 + gr;
            const int n = n0 + wn * 64 + nt * 8 + gc;
            const float2 av = *reinterpret_cast<const float2*>(att_s + n);
            const float2 dv = *reinterpret_cast<const float2*>(att_d + n);
            s0 += acc[mt][nt][0] * av.x + acc[mt][nt][1] * av.y;
            s1 += acc[mt][nt][2] * av.x + acc[mt][nt][3] * av.y;
            d0 += acc[mt][nt][0] * dv.x + acc[mt][nt][1] * dv.y;
            d1 += acc[mt][nt][2] * dv.x + acc[mt][nt][3] * dv.y;
            if (m < M)
                *reinterpret_cast<float2*>(&C[(size_t)m * DIM + n]) =
                    make_float2(acc[mt][nt][0], acc[mt][nt][1]);
            if (m + 8 < M)
                *reinterpret_cast<float2*>(&C[(size_t)(m + 8) * DIM + n]) =
                    make_float2(acc[mt][nt][2], acc[mt][nt][3]);
        }
#pragma unroll
        for (int o = 1; o < 4; o <<= 1) {
            s0 += __shfl_xor_sync(0xffffffffu, s0, o);
            s1 += __shfl_xor_sync(0xffffffffu, s1, o);
            d0 += __shfl_xor_sync(0xffffffffu, d0, o);
            d1 += __shfl_xor_sync(0xffffffffu, d1, o);
        }
        if ((lane & 3) == 0) {
            const int m = m0 + wm * 64 + mt * 16 + gr;
            if (m < M)     { atomicAdd(&as_[m], s0);     atomicAdd(&ad_[m], d0); }
            if (m + 8 < M) { atomicAdd(&as_[m + 8], s1); atomicAdd(&ad_[m + 8], d1); }
        }
    }
}

// ---------------- fp16 split conversions ----------------
__global__ void split_x(const float* __restrict__ x, __half* __restrict__ hi,
                        __half* __restrict__ lo, int total) {
    const int i = blockIdx.x * blockDim.x + threadIdx.x;
    if (i >= total) return;
    const float v = x[i];
    const __half h = __float2half(v);
    hi[i] = h;
    lo[i] = __float2half(v - __half2float(h));
}

// batched: z=0 -> W1, z=1 -> W2.  W [K][N] row-major -> Wt fp16 [N][K]
__global__ void split_wT(const float* __restrict__ Wa, const float* __restrict__ Wb,
                         __half* __restrict__ hA, __half* __restrict__ hB) {
    const float* W = blockIdx.z ? Wb : Wa;
    __half* hiT = blockIdx.z ? hB : hA;
    __shared__ float t[32][33];
    const int bx = blockIdx.x * 32, by = blockIdx.y * 32;
    const int tx = threadIdx.x, ty = threadIdx.y;
    #pragma unroll
    for (int j = 0; j < 4; j++)
        t[ty + j * 8][tx] = W[(size_t)(by + ty + j * 8) * DIM + bx + tx];
    __syncthreads();
    #pragma unroll
    for (int j = 0; j < 4; j++) {
        const float v = t[tx][ty + j * 8];
        hiT[(size_t)(bx + ty + j * 8) * DIM + by + tx] = __float2half(v);
    }
}

// zero cnt + both layers' attention accumulators in one launch
__global__ void zero_all(int* __restrict__ cnt,
                         float* __restrict__ a1, float* __restrict__ d1,
                         float* __restrict__ a2, float* __restrict__ d2, int n) {
    const int i = blockIdx.x * blockDim.x + threadIdx.x;
    if (i < n) { cnt[i] = 0; a1[i] = 0.f; d1[i] = 0.f; a2[i] = 0.f; d2[i] = 0.f; }
}

// ---------------- CSR build ----------------
__global__ void hist_k(const int* __restrict__ ei, int nE, int nN, int* __restrict__ cnt) {
    const int e = blockIdx.x * blockDim.x + threadIdx.x;
    if (e >= nE + nN) return;
    const int d = (e < nE) ? ei[nE + e] : (e - nE);
    atomicAdd(&cnt[d], 1);
}
__global__ void scan_rowptr(const int* __restrict__ cnt, int* __restrict__ rowptr,
                            int* __restrict__ cursor, int n) {
    __shared__ int sh[32];
    __shared__ int carry_sh;
    const int tid = threadIdx.x, lane = tid & 31, wid = tid >> 5;
    if (tid == 0) carry_sh = 0;
    __syncthreads();
    for (int base = 0; base < n; base += 1024) {
        const int i = base + tid;
        const int v = (i < n) ? cnt[i] : 0;
        int x = v;
#pragma unroll
        for (int o = 1; o < 32; o <<= 1) {
            int y = __shfl_up_sync(0xffffffffu, x, o);
            if (lane >= o) x += y;
        }
        if (lane == 31) sh[wid] = x;
        __syncthreads();
        if (wid == 0) {
            int s = sh[lane];
#pragma unroll
            for (int o = 1; o < 32; o <<= 1) {
                int y = __shfl_up_sync(0xffffffffu, s, o);
                if (lane >= o) s += y;
            }
            sh[lane] = s;
        }
        __syncthreads();
        const int incl = x + (wid > 0 ? sh[wid - 1] : 0);
        const int carry = carry_sh;
        if (i < n) { rowptr[i] = carry + incl - v; cursor[i] = carry + incl - v; }
        __syncthreads();
        if (tid == 1023) carry_sh = carry + incl;
        __syncthreads();
    }
    if (threadIdx.x == 0) rowptr[n] = carry_sh;
}
__global__ void fill_csr(const int* __restrict__ ei, int nE, int nN,
                         int* __restrict__ cursor, int* __restrict__ srcs) {
    const int e = blockIdx.x * blockDim.x + threadIdx.x;
    if (e >= nE + nN) return;
    int s, d;
    if (e < nE) { s = ei[e]; d = ei[nE + e]; }
    else        { s = d = e - nE; }
    const int pos = atomicAdd(&cursor[d], 1);
    srcs[pos] = s;
}

// ---------------- fused per-node softmax + gather ----------------
// mode 0: write float out (layer 2, no relu)
// mode 1: relu, then write fp16 hi/lo split (layer 1 -> layer 2 GEMM operands)
__global__ void gat_gather(const int* __restrict__ rowptr, const int* __restrict__ srcs,
                           const float* __restrict__ as_, const float* __restrict__ ad_,
                           const float* __restrict__ h, const float* __restrict__ bias,
                           float* __restrict__ outF,
                           __half* __restrict__ outH,
                           __half* __restrict__ outL,
                           int n, int mode) {
    const int node = blockIdx.x * (blockDim.x >> 5) + (threadIdx.x >> 5);
    const int lane = threadIdx.x & 31;
    if (node >= n) return;
    const int beg = rowptr[node], end = rowptr[node + 1];
    const float adn = ad_[node];

    float mx = -INFINITY;
    for (int j = beg + lane; j < end; j += 32) {
        float v = as_[srcs[j]] + adn;
        v = v > 0.f ? v : 0.2f * v;
        mx = fmaxf(mx, v);
    }
#pragma unroll
    for (int o = 16; o; o >>= 1) mx = fmaxf(mx, __shfl_xor_sync(0xffffffffu, mx, o));

    float den = 0.f;
    for (int j = beg + lane; j < end; j += 32) {
        float v = as_[srcs[j]] + adn;
        v = v > 0.f ? v : 0.2f * v;
        den += expf(v - mx);
    }
#pragma unroll
    for (int o = 16; o; o >>= 1) den += __shfl_xor_sync(0xffffffffu, den, o);
    const float inv = 1.f / den;

    float4 acc[DIM / 128];
#pragma unroll
    for (int q = 0; q < DIM / 128; q++) acc[q] = make_float4(0.f, 0.f, 0.f, 0.f);

    for (int j0 = beg; j0 < end; j0 += 32) {
        const int j = j0 + lane;
        float w = 0.f; int s = 0;
        if (j < end) {
            s = srcs[j];
            float v = as_[s] + adn;
            v = v > 0.f ? v : 0.2f * v;
            w = expf(v - mx) * inv;
        }
        const int cnt = min(32, end - j0);
        for (int t = 0; t < cnt; t++) {
            const float wt = __shfl_sync(0xffffffffu, w, t);
            const int   st = __shfl_sync(0xffffffffu, s, t);
            const float4* hr = reinterpret_cast<const float4*>(h + (size_t)st * DIM);
#pragma unroll
            for (int q = 0; q < DIM / 128; q++) {
                const float4 v = hr[lane + 32 * q];
                acc[q].x += wt * v.x; acc[q].y += wt * v.y;
                acc[q].z += wt * v.z; acc[q].w += wt * v.w;
            }
        }
    }

    const float4* b4 = reinterpret_cast<const float4*>(bias);
#pragma unroll
    for (int q = 0; q < DIM / 128; q++) {
        const float4 bv = b4[lane + 32 * q];
        float4 r = make_float4(acc[q].x + bv.x, acc[q].y + bv.y,
                               acc[q].z + bv.z, acc[q].w + bv.w);
        if (mode == 1) {
            r.x = fmaxf(r.x, 0.f); r.y = fmaxf(r.y, 0.f);
            r.z = fmaxf(r.z, 0.f); r.w = fmaxf(r.w, 0.f);
            const size_t off = (size_t)node * DIM + (lane + 32 * q) * 4;
            const __half hx = __float2half(r.x), hy = __float2half(r.y);
            const __half hz = __float2half(r.z), hw = __float2half(r.w);
            __half2 h01 = __halves2half2(hx, hy);
            __half2 h23 = __halves2half2(hz, hw);
            __half2 l01 = __halves2half2(__float2half(r.x - __half2float(hx)),
                                         __float2half(r.y - __half2float(hy)));
            __half2 l23 = __halves2half2(__float2half(r.z - __half2float(hz)),
                                         __float2half(r.w - __half2float(hw)));
            uint2 hp = make_uint2(*(uint32_t*)&h01, *(uint32_t*)&h23);
            uint2 lp = make_uint2(*(uint32_t*)&l01, *(uint32_t*)&l23);
            *reinterpret_cast<uint2*>(outH + off) = hp;
            *reinterpret_cast<uint2*>(outL + off) = lp;
        } else {
            float4* o4 = reinterpret_cast<float4*>(outF + (size_t)node * DIM);
            o4[lane + 32 * q] = r;
        }
    }
}

// ---------------- launch ----------------
extern "C" void kernel_launch(void* const* d_in, const int* in_sizes, int n_in,
                              void* d_out, int out_size) {
    const float* x    = (const float*)d_in[0];
    const int*   ei   = (const int*)d_in[1];     // int32 edge_index [2, E]
    const float* W1   = (const float*)d_in[2];
    const float* as1  = (const float*)d_in[3];
    const float* ad1  = (const float*)d_in[4];
    const float* b1   = (const float*)d_in[5];
    const float* W2   = (const float*)d_in[6];
    const float* as2  = (const float*)d_in[7];
    const float* ad2  = (const float*)d_in[8];
    const float* b2   = (const float*)d_in[9];

    const int n_nodes = in_sizes[0] / DIM;
    const int n_edges = in_sizes[1] / 2;
    const int tot     = n_edges + n_nodes;

    float *h, *asL1, *adL1, *asL2, *adL2;
    int *cnt, *rowptr, *cursor, *srcs;
    __half *ah, *al, *w1h, *w2h;
    cudaGetSymbolAddress((void**)&h,      g_h);
    cudaGetSymbolAddress((void**)&asL1,   g_as1);
    cudaGetSymbolAddress((void**)&adL1,   g_ad1);
    cudaGetSymbolAddress((void**)&asL2,   g_as2);
    cudaGetSymbolAddress((void**)&adL2,   g_ad2);
    cudaGetSymbolAddress((void**)&cnt,    g_cnt);
    cudaGetSymbolAddress((void**)&rowptr, g_rowptr);
    cudaGetSymbolAddress((void**)&cursor, g_cursor);
    cudaGetSymbolAddress((void**)&srcs,   g_srcs);
    cudaGetSymbolAddress((void**)&ah,     g_ah);
    cudaGetSymbolAddress((void**)&al,     g_al);
    cudaGetSymbolAddress((void**)&w1h,    g_w1h);
    cudaGetSymbolAddress((void**)&w2h,    g_w2h);

    cudaFuncSetAttribute(gemm_mma, cudaFuncAttributeMaxDynamicSharedMemorySize, SM_TOT);

    const int nd_total = n_nodes * DIM;
    const dim3 gemm_grid(DIM / BN, (n_nodes + BM - 1) / BM);
    const dim3 tr_grid(DIM / 32, DIM / 32, 2), tr_blk(32, 8);

    // 0: zero everything (cnt + both layers' attention accumulators)
    zero_all<<<(n_nodes + 255) / 256, 256>>>(cnt, asL1, adL1, asL2, adL2, n_nodes);
    // 1: both weight conversions (batched, fp16)
    split_wT<<<tr_grid, tr_blk>>>(W1, W2, w1h, w2h);
    // 2: layer-1 input split (fp16 hi/lo)
    split_x<<<(nd_total + 255) / 256, 256>>>(x, ah, al, nd_total);
    // 3: layer-1 GEMM  <-- ncu capture slot
    gemm_mma<<<gemm_grid, 256, SM_TOT>>>(n_nodes, ah, al, w1h,
                                         as1, ad1, asL1, adL1, h);
    // 4-6: CSR build (only needed by gather)
    hist_k<<<(tot + 255) / 256, 256>>>(ei, n_edges, n_nodes, cnt);
    scan_rowptr<<<1, 1024>>>(cnt, rowptr, cursor, n_nodes);
    fill_csr<<<(tot + 255) / 256, 256>>>(ei, n_edges, n_nodes, cursor, srcs);
    // 7: layer-1 gather (writes fp16 split for layer 2)
    gat_gather<<<(n_nodes + 7) / 8, 256>>>(rowptr, srcs, asL1, adL1, h, b1,
                                           nullptr, ah, al, n_nodes, 1);
    // 8: layer-2 GEMM
    gemm_mma<<<gemm_grid, 256, SM_TOT>>>(n_nodes, ah, al, w2h,
                                         as2, ad2, asL2, adL2, h);
    // 9: layer-2 gather -> output
    gat_gather<<<(n_nodes + 7) / 8, 256>>>(rowptr, srcs, asL2, adL2, h, b2,
                                           (float*)d_out, nullptr, nullptr, n_nodes, 0);
}

// round 15
// speedup vs baseline: 1.3837x; 1.0631x over previous
#include <cuda_runtime.h>
#include <cuda_fp16.h>
#include <math.h>
#include <stdint.h>

#define DIM   768
#define MAXN  10000
#define MAXE  100000

// ---------------- scratch (static device globals; no allocation) ----------------
__device__ __half g_hh[MAXN * DIM];    // h = x @ W in fp16 (per-layer, reused)
__device__ float g_as1[MAXN], g_ad1[MAXN];
__device__ float g_as2[MAXN], g_ad2[MAXN];
__device__ int   g_cnt[MAXN];
__device__ int   g_rowptr[MAXN + 1];
__device__ int   g_cursor[MAXN];
__device__ int   g_srcs[MAXE + MAXN];
// fp16 split operands: A = Ah + Al (exact to ~2^-24); B = Bh (fp16, ~2^-12)
__device__ __half g_ah[MAXN * DIM];
__device__ __half g_al[MAXN * DIM];
__device__ __half g_w1h[DIM * DIM];    // W1^T fp16
__device__ __half g_w2h[DIM * DIM];    // W2^T fp16

// ---------------- mma.sync helpers (sm_80+ path; valid on plain sm_103) ------
__device__ __forceinline__ void mma_f16(float* c, const uint32_t* a, const uint32_t* b) {
    asm volatile(
        "mma.sync.aligned.m16n8k16.row.col.f32.f16.f16.f32 "
        "{%0,%1,%2,%3}, {%4,%5,%6,%7}, {%8,%9}, {%0,%1,%2,%3};"
        : "+f"(c[0]), "+f"(c[1]), "+f"(c[2]), "+f"(c[3])
        : "r"(a[0]), "r"(a[1]), "r"(a[2]), "r"(a[3]), "r"(b[0]), "r"(b[1]));
}
__device__ __forceinline__ void ldm4(uint32_t* r, uint32_t addr) {
    asm volatile("ldmatrix.sync.aligned.m8n8.x4.shared.b16 {%0,%1,%2,%3}, [%4];"
                 : "=r"(r[0]), "=r"(r[1]), "=r"(r[2]), "=r"(r[3]) : "r"(addr));
}
__device__ __forceinline__ void cpa16(uint32_t dst, const void* src, int src_bytes) {
    asm volatile("cp.async.ca.shared.global [%0], [%1], 16, %2;"
                 :: "r"(dst), "l"(src), "r"(src_bytes));
}
__device__ __forceinline__ void cpa_commit() {
    asm volatile("cp.async.commit_group;" ::: "memory");
}
template <int N>
__device__ __forceinline__ void cpa_wait() {
    asm volatile("cp.async.wait_group %0;" :: "n"(N) : "memory");
}

// ---------------- tensor-core GEMM + fused attention dots ----------------
// C = Ah*Bh + Al*Bh (fp32 accum, fp16 C store). CTA tile 128x256, BK=32.
// 256 threads, 8 warps (2x4), warp tile 64x64. 3-stage cp.async pipeline.
#define BM       128
#define BN       256
#define SM_AH    0
#define SM_AL    10240                 // 128 rows * 80 B
#define SM_BH    20480                 // 256 rows * 80 B
#define SM_STAGE 40960
#define SM_TOT   (SM_STAGE * 3)        // 122880 B

__global__ __launch_bounds__(256, 1) void gemm_mma(
        int M,
        const __half* __restrict__ Ah, const __half* __restrict__ Al,
        const __half* __restrict__ Bh,
        const float* __restrict__ att_s, const float* __restrict__ att_d,
        float* __restrict__ as_, float* __restrict__ ad_,
        __half* __restrict__ C) {
    extern __shared__ char dsm[];
    const uint32_t sb = (uint32_t)__cvta_generic_to_shared(dsm);

    const int tid  = threadIdx.x;
    const int lane = tid & 31;
    const int warp = tid >> 5;           // 0..7
    const int wm   = warp >> 2;          // 0..1  (64 rows each)
    const int wn   = warp & 3;           // 0..3  (64 cols each)
    const int m0   = blockIdx.y * BM;
    const int n0   = blockIdx.x * BN;
    const int rowsv = min(BM, M - m0);

    float acc[4][8][4];                  // mt, nt(8 cols of 8), frag
#pragma unroll
    for (int i = 0; i < 4; i++)
#pragma unroll
        for (int j = 0; j < 8; j++)
#pragma unroll
            for (int q = 0; q < 4; q++) acc[i][j][q] = 0.f;

    const int amat = lane >> 3, ar = lane & 7;
    const int a_row_off = ((amat & 1) << 3) + ar;
    const int a_col_off = (amat >> 1) << 3;
    const int b_row_off = ((amat >> 1) << 3) + ar;
    const int b_col_off = (amat & 1) << 3;

    const int NT = DIM / 32;

    // stage one 32-K chunk: A 512 16B-chunks x2 arrays, B 1024 x1 array
    auto stage = [&](int s, int k0) {
        const uint32_t base = sb + s * SM_STAGE;
#pragma unroll
        for (int i = tid; i < 512; i += 256) {
            const int row = i >> 2, chk = i & 3;
            const uint32_t so = (uint32_t)(row * 80 + chk * 16);
            const bool av = row < rowsv;
            const size_t ga = (size_t)(m0 + (av ? row : 0)) * DIM + k0 + chk * 8;
            const int asz = av ? 16 : 0;
            cpa16(base + SM_AH + so, Ah + ga, asz);
            cpa16(base + SM_AL + so, Al + ga, asz);
        }
#pragma unroll
        for (int i = tid; i < 1024; i += 256) {
            const int row = i >> 2, chk = i & 3;
            const uint32_t so = (uint32_t)(row * 80 + chk * 16);
            const size_t gb = (size_t)(n0 + row) * DIM + k0 + chk * 8;
            cpa16(base + SM_BH + so, Bh + gb, 16);
        }
    };

    stage(0, 0);  cpa_commit();
    stage(1, 32); cpa_commit();

    for (int it = 0; it < NT; it++) {
        cpa_wait<1>();            // buffer it%3's group complete
        __syncthreads();          // prev readers of (it+2)%3 done
        if (it + 2 < NT) { stage((it + 2) % 3, (it + 2) * 32); cpa_commit(); }

        const uint32_t bA = sb + (it % 3) * SM_STAGE;
#pragma unroll
        for (int kc = 0; kc < 2; kc++) {
            uint32_t ah[4][4], al[4][4];
#pragma unroll
            for (int mt = 0; mt < 4; mt++) {
                const uint32_t off =
                    (uint32_t)((wm * 64 + mt * 16 + a_row_off) * 80 +
                               (kc * 16 + a_col_off) * 2);
                ldm4(ah[mt], bA + SM_AH + off);
                ldm4(al[mt], bA + SM_AL + off);
            }
#pragma unroll
            for (int p = 0; p < 4; p++) {    // 16-col group within warp's 64
                uint32_t bh4[4];
                const uint32_t off =
                    (uint32_t)((wn * 64 + p * 16 + b_row_off) * 80 +
                               (kc * 16 + b_col_off) * 2);
                ldm4(bh4, bA + SM_BH + off);
#pragma unroll
                for (int mt = 0; mt < 4; mt++)
#pragma unroll
                    for (int q = 0; q < 2; q++)
                        mma_f16(acc[mt][p * 2 + q], ah[mt], &bh4[q * 2]);
#pragma unroll
                for (int mt = 0; mt < 4; mt++)
#pragma unroll
                    for (int q = 0; q < 2; q++)
                        mma_f16(acc[mt][p * 2 + q], al[mt], &bh4[q * 2]);
            }
        }
    }
    __syncthreads();

    // ---- epilogue: fp16 C store + fused attention dot partials (fp32) ----
    const int gr = lane >> 2, gc = (lane & 3) * 2;
#pragma unroll
    for (int mt = 0; mt < 4; mt++) {
        float s0 = 0.f, s1 = 0.f, d0 = 0.f, d1 = 0.f;
#pragma unroll
        for (int nt = 0; nt < 8; nt++) {
            const int m = m0 + wm * 64 + mt * 16 + gr;
            const int n = n0 + wn * 64 + nt * 8 + gc;
            const float2 av = *reinterpret_cast<const float2*>(att_s + n);
            const float2 dv = *reinterpret_cast<const float2*>(att_d + n);
            s0 += acc[mt][nt][0] * av.x + acc[mt][nt][1] * av.y;
            s1 += acc[mt][nt][2] * av.x + acc[mt][nt][3] * av.y;
            d0 += acc[mt][nt][0] * dv.x + acc[mt][nt][1] * dv.y;
            d1 += acc[mt][nt][2] * dv.x + acc[mt][nt][3] * dv.y;
            if (m < M) {
                __half2 c01 = __floats2half2_rn(acc[mt][nt][0], acc[mt][nt][1]);
                *reinterpret_cast<__half2*>(&C[(size_t)m * DIM + n]) = c01;
            }
            if (m + 8 < M) {
                __half2 c23 = __floats2half2_rn(acc[mt][nt][2], acc[mt][nt][3]);
                *reinterpret_cast<__half2*>(&C[(size_t)(m + 8) * DIM + n]) = c23;
            }
        }
#pragma unroll
        for (int o = 1; o < 4; o <<= 1) {
            s0 += __shfl_xor_sync(0xffffffffu, s0, o);
            s1 += __shfl_xor_sync(0xffffffffu, s1, o);
            d0 += __shfl_xor_sync(0xffffffffu, d0, o);
            d1 += __shfl_xor_sync(0xffffffffu, d1, o);
        }
        if ((lane & 3) == 0) {
            const int m = m0 + wm * 64 + mt * 16 + gr;
            if (m < M)     { atomicAdd(&as_[m], s0);     atomicAdd(&ad_[m], d0); }
            if (m + 8 < M) { atomicAdd(&as_[m + 8], s1); atomicAdd(&ad_[m + 8], d1); }
        }
    }
}

// ---------------- fp16 split conversions ----------------
__global__ void split_x(const float* __restrict__ x, __half* __restrict__ hi,
                        __half* __restrict__ lo, int total) {
    const int i = blockIdx.x * blockDim.x + threadIdx.x;
    if (i >= total) return;
    const float v = x[i];
    const __half h = __float2half(v);
    hi[i] = h;
    lo[i] = __float2half(v - __half2float(h));
}

// batched: z=0 -> W1, z=1 -> W2.  W [K][N] row-major -> Wt fp16 [N][K]
__global__ void split_wT(const float* __restrict__ Wa, const float* __restrict__ Wb,
                         __half* __restrict__ hA, __half* __restrict__ hB) {
    const float* W = blockIdx.z ? Wb : Wa;
    __half* hiT = blockIdx.z ? hB : hA;
    __shared__ float t[32][33];
    const int bx = blockIdx.x * 32, by = blockIdx.y * 32;
    const int tx = threadIdx.x, ty = threadIdx.y;
    #pragma unroll
    for (int j = 0; j < 4; j++)
        t[ty + j * 8][tx] = W[(size_t)(by + ty + j * 8) * DIM + bx + tx];
    __syncthreads();
    #pragma unroll
    for (int j = 0; j < 4; j++) {
        const float v = t[tx][ty + j * 8];
        hiT[(size_t)(bx + ty + j * 8) * DIM + by + tx] = __float2half(v);
    }
}

// zero cnt + both layers' attention accumulators in one launch
__global__ void zero_all(int* __restrict__ cnt,
                         float* __restrict__ a1, float* __restrict__ d1,
                         float* __restrict__ a2, float* __restrict__ d2, int n) {
    const int i = blockIdx.x * blockDim.x + threadIdx.x;
    if (i < n) { cnt[i] = 0; a1[i] = 0.f; d1[i] = 0.f; a2[i] = 0.f; d2[i] = 0.f; }
}

// ---------------- CSR build ----------------
__global__ void hist_k(const int* __restrict__ ei, int nE, int nN, int* __restrict__ cnt) {
    const int e = blockIdx.x * blockDim.x + threadIdx.x;
    if (e >= nE + nN) return;
    const int d = (e < nE) ? ei[nE + e] : (e - nE);
    atomicAdd(&cnt[d], 1);
}
__global__ void scan_rowptr(const int* __restrict__ cnt, int* __restrict__ rowptr,
                            int* __restrict__ cursor, int n) {
    __shared__ int sh[32];
    __shared__ int carry_sh;
    const int tid = threadIdx.x, lane = tid & 31, wid = tid >> 5;
    if (tid == 0) carry_sh = 0;
    __syncthreads();
    for (int base = 0; base < n; base += 1024) {
        const int i = base + tid;
        const int v = (i < n) ? cnt[i] : 0;
        int x = v;
#pragma unroll
        for (int o = 1; o < 32; o <<= 1) {
            int y = __shfl_up_sync(0xffffffffu, x, o);
            if (lane >= o) x += y;
        }
        if (lane == 31) sh[wid] = x;
        __syncthreads();
        if (wid == 0) {
            int s = sh[lane];
#pragma unroll
            for (int o = 1; o < 32; o <<= 1) {
                int y = __shfl_up_sync(0xffffffffu, s, o);
                if (lane >= o) s += y;
            }
            sh[lane] = s;
        }
        __syncthreads();
        const int incl = x + (wid > 0 ? sh[wid - 1] : 0);
        const int carry = carry_sh;
        if (i < n) { rowptr[i] = carry + incl - v; cursor[i] = carry + incl - v; }
        __syncthreads();
        if (tid == 1023) carry_sh = carry + incl;
        __syncthreads();
    }
    if (threadIdx.x == 0) rowptr[n] = carry_sh;
}
__global__ void fill_csr(const int* __restrict__ ei, int nE, int nN,
                         int* __restrict__ cursor, int* __restrict__ srcs) {
    const int e = blockIdx.x * blockDim.x + threadIdx.x;
    if (e >= nE + nN) return;
    int s, d;
    if (e < nE) { s = ei[e]; d = ei[nE + e]; }
    else        { s = d = e - nE; }
    const int pos = atomicAdd(&cursor[d], 1);
    srcs[pos] = s;
}

// ---------------- fused per-node softmax + gather (fp16 h rows) --------------
// mode 0: write float out (layer 2, no relu)
// mode 1: relu, then write fp16 hi/lo split (layer 1 -> layer 2 GEMM operands)
__global__ void gat_gather(const int* __restrict__ rowptr, const int* __restrict__ srcs,
                           const float* __restrict__ as_, const float* __restrict__ ad_,
                           const __half* __restrict__ h, const float* __restrict__ bias,
                           float* __restrict__ outF,
                           __half* __restrict__ outH,
                           __half* __restrict__ outL,
                           int n, int mode) {
    const int node = blockIdx.x * (blockDim.x >> 5) + (threadIdx.x >> 5);
    const int lane = threadIdx.x & 31;
    if (node >= n) return;
    const int beg = rowptr[node], end = rowptr[node + 1];
    const float adn = ad_[node];

    float mx = -INFINITY;
    for (int j = beg + lane; j < end; j += 32) {
        float v = as_[srcs[j]] + adn;
        v = v > 0.f ? v : 0.2f * v;
        mx = fmaxf(mx, v);
    }
#pragma unroll
    for (int o = 16; o; o >>= 1) mx = fmaxf(mx, __shfl_xor_sync(0xffffffffu, mx, o));

    float den = 0.f;
    for (int j = beg + lane; j < end; j += 32) {
        float v = as_[srcs[j]] + adn;
        v = v > 0.f ? v : 0.2f * v;
        den += expf(v - mx);
    }
#pragma unroll
    for (int o = 16; o; o >>= 1) den += __shfl_xor_sync(0xffffffffu, den, o);
    const float inv = 1.f / den;

    // 3 x uint4 (8 halves each) per lane covers 768 halves per row
    float acc[3][8];
#pragma unroll
    for (int q = 0; q < 3; q++)
#pragma unroll
        for (int e8 = 0; e8 < 8; e8++) acc[q][e8] = 0.f;

    for (int j0 = beg; j0 < end; j0 += 32) {
        const int j = j0 + lane;
        float w = 0.f; int s = 0;
        if (j < end) {
            s = srcs[j];
            float v = as_[s] + adn;
            v = v > 0.f ? v : 0.2f * v;
            w = expf(v - mx) * inv;
        }
        const int cnt = min(32, end - j0);
        for (int t = 0; t < cnt; t++) {
            const float wt = __shfl_sync(0xffffffffu, w, t);
            const int   st = __shfl_sync(0xffffffffu, s, t);
            const uint4* hr = reinterpret_cast<const uint4*>(h + (size_t)st * DIM);
#pragma unroll
            for (int q = 0; q < 3; q++) {
                const uint4 v = hr[lane + 32 * q];
                const __half2* p = reinterpret_cast<const __half2*>(&v);
#pragma unroll
                for (int k = 0; k < 4; k++) {
                    const float2 f = __half22float2(p[k]);
                    acc[q][k * 2 + 0] += wt * f.x;
                    acc[q][k * 2 + 1] += wt * f.y;
                }
            }
        }
    }

#pragma unroll
    for (int q = 0; q < 3; q++) {
        const int col0 = (lane + 32 * q) * 8;
        const float4 b0 = *reinterpret_cast<const float4*>(bias + col0);
        const float4 b1 = *reinterpret_cast<const float4*>(bias + col0 + 4);
        float r[8];
        r[0] = acc[q][0] + b0.x; r[1] = acc[q][1] + b0.y;
        r[2] = acc[q][2] + b0.z; r[3] = acc[q][3] + b0.w;
        r[4] = acc[q][4] + b1.x; r[5] = acc[q][5] + b1.y;
        r[6] = acc[q][6] + b1.z; r[7] = acc[q][7] + b1.w;
        if (mode == 1) {
#pragma unroll
            for (int k = 0; k < 8; k++) r[k] = fmaxf(r[k], 0.f);
            __half hi8[8], lo8[8];
#pragma unroll
            for (int k = 0; k < 8; k++) {
                hi8[k] = __float2half(r[k]);
                lo8[k] = __float2half(r[k] - __half2float(hi8[k]));
            }
            const size_t off = (size_t)node * DIM + col0;
            *reinterpret_cast<uint4*>(outH + off) = *reinterpret_cast<uint4*>(hi8);
            *reinterpret_cast<uint4*>(outL + off) = *reinterpret_cast<uint4*>(lo8);
        } else {
            float* o = outF + (size_t)node * DIM + col0;
            *reinterpret_cast<float4*>(o)     = make_float4(r[0], r[1], r[2], r[3]);
            *reinterpret_cast<float4*>(o + 4) = make_float4(r[4], r[5], r[6], r[7]);
        }
    }
}

// ---------------- launch ----------------
extern "C" void kernel_launch(void* const* d_in, const int* in_sizes, int n_in,
                              void* d_out, int out_size) {
    const float* x    = (const float*)d_in[0];
    const int*   ei   = (const int*)d_in[1];     // int32 edge_index [2, E]
    const float* W1   = (const float*)d_in[2];
    const float* as1  = (const float*)d_in[3];
    const float* ad1  = (const float*)d_in[4];
    const float* b1   = (const float*)d_in[5];
    const float* W2   = (const float*)d_in[6];
    const float* as2  = (const float*)d_in[7];
    const float* ad2  = (const float*)d_in[8];
    const float* b2   = (const float*)d_in[9];

    const int n_nodes = in_sizes[0] / DIM;
    const int n_edges = in_sizes[1] / 2;
    const int tot     = n_edges + n_nodes;

    float *asL1, *adL1, *asL2, *adL2;
    int *cnt, *rowptr, *cursor, *srcs;
    __half *hh, *ah, *al, *w1h, *w2h;
    cudaGetSymbolAddress((void**)&hh,     g_hh);
    cudaGetSymbolAddress((void**)&asL1,   g_as1);
    cudaGetSymbolAddress((void**)&adL1,   g_ad1);
    cudaGetSymbolAddress((void**)&asL2,   g_as2);
    cudaGetSymbolAddress((void**)&adL2,   g_ad2);
    cudaGetSymbolAddress((void**)&cnt,    g_cnt);
    cudaGetSymbolAddress((void**)&rowptr, g_rowptr);
    cudaGetSymbolAddress((void**)&cursor, g_cursor);
    cudaGetSymbolAddress((void**)&srcs,   g_srcs);
    cudaGetSymbolAddress((void**)&ah,     g_ah);
    cudaGetSymbolAddress((void**)&al,     g_al);
    cudaGetSymbolAddress((void**)&w1h,    g_w1h);
    cudaGetSymbolAddress((void**)&w2h,    g_w2h);

    cudaFuncSetAttribute(gemm_mma, cudaFuncAttributeMaxDynamicSharedMemorySize, SM_TOT);

    const int nd_total = n_nodes * DIM;
    const dim3 gemm_grid(DIM / BN, (n_nodes + BM - 1) / BM);
    const dim3 tr_grid(DIM / 32, DIM / 32, 2), tr_blk(32, 8);

    // 0: zero everything (cnt + both layers' attention accumulators)
    zero_all<<<(n_nodes + 255) / 256, 256>>>(cnt, asL1, adL1, asL2, adL2, n_nodes);
    // 1: both weight conversions (batched, fp16)
    split_wT<<<tr_grid, tr_blk>>>(W1, W2, w1h, w2h);
    // 2: layer-1 input split (fp16 hi/lo)
    split_x<<<(nd_total + 255) / 256, 256>>>(x, ah, al, nd_total);
    // 3: layer-1 GEMM  <-- ncu capture slot
    gemm_mma<<<gemm_grid, 256, SM_TOT>>>(n_nodes, ah, al, w1h,
                                         as1, ad1, asL1, adL1, hh);
    // 4-6: CSR build (only needed by gather)
    hist_k<<<(tot + 255) / 256, 256>>>(ei, n_edges, n_nodes, cnt);
    scan_rowptr<<<1, 1024>>>(cnt, rowptr, cursor, n_nodes);
    fill_csr<<<(tot + 255) / 256, 256>>>(ei, n_edges, n_nodes, cursor, srcs);
    // 7: layer-1 gather (writes fp16 split for layer 2)
    gat_gather<<<(n_nodes + 7) / 8, 256>>>(rowptr, srcs, asL1, adL1, hh, b1,
                                           nullptr, ah, al, n_nodes, 1);
    // 8: layer-2 GEMM
    gemm_mma<<<gemm_grid, 256, SM_TOT>>>(n_nodes, ah, al, w2h,
                                         as2, ad2, asL2, adL2, hh);
    // 9: layer-2 gather -> output
    gat_gather<<<(n_nodes + 7) / 8, 256>>>(rowptr, srcs, asL2, adL2, hh, b2,
                                           (float*)d_out, nullptr, nullptr, n_nodes, 0);
}

// round 16
// speedup vs baseline: 1.7751x; 1.2828x over previous
#include <cuda_runtime.h>
#include <cuda_fp16.h>
#include <math.h>
#include <stdint.h>

#define DIM   768
#define MAXN  10000
#define MAXE  100000

// ---------------- scratch (static device globals; no allocation) ----------------
__device__ __half g_hh[MAXN * DIM];    // h = x @ W in fp16 (per-layer, reused)
__device__ float g_as1[MAXN], g_ad1[MAXN];
__device__ float g_as2[MAXN], g_ad2[MAXN];
__device__ int   g_cnt[MAXN];
__device__ int   g_rowptr[MAXN + 1];
__device__ int   g_cursor[MAXN];
__device__ int   g_srcs[MAXE + MAXN];
// fp16 operands (single-rounded: ~2^-12 relative each)
__device__ __half g_ah[MAXN * DIM];
__device__ __half g_w1h[DIM * DIM];    // W1^T fp16
__device__ __half g_w2h[DIM * DIM];    // W2^T fp16

// ---------------- mma.sync helpers (sm_80+ path; valid on plain sm_103) ------
__device__ __forceinline__ void mma_f16(float* c, const uint32_t* a, const uint32_t* b) {
    asm volatile(
        "mma.sync.aligned.m16n8k16.row.col.f32.f16.f16.f32 "
        "{%0,%1,%2,%3}, {%4,%5,%6,%7}, {%8,%9}, {%0,%1,%2,%3};"
        : "+f"(c[0]), "+f"(c[1]), "+f"(c[2]), "+f"(c[3])
        : "r"(a[0]), "r"(a[1]), "r"(a[2]), "r"(a[3]), "r"(b[0]), "r"(b[1]));
}
__device__ __forceinline__ void ldm4(uint32_t* r, uint32_t addr) {
    asm volatile("ldmatrix.sync.aligned.m8n8.x4.shared.b16 {%0,%1,%2,%3}, [%4];"
                 : "=r"(r[0]), "=r"(r[1]), "=r"(r[2]), "=r"(r[3]) : "r"(addr));
}
__device__ __forceinline__ void cpa16(uint32_t dst, const void* src, int src_bytes) {
    asm volatile("cp.async.ca.shared.global [%0], [%1], 16, %2;"
                 :: "r"(dst), "l"(src), "r"(src_bytes));
}
__device__ __forceinline__ void cpa_commit() {
    asm volatile("cp.async.commit_group;" ::: "memory");
}
template <int N>
__device__ __forceinline__ void cpa_wait() {
    asm volatile("cp.async.wait_group %0;" :: "n"(N) : "memory");
}

// ---------------- tensor-core GEMM + fused attention dots ----------------
// C = A*B (fp16 operands, fp32 accum, fp16 C store). CTA tile 128x256, BK=32.
// 256 threads, 8 warps (2x4), warp tile 64x64. 3-stage cp.async pipeline.
#define BM       128
#define BN       256
#define SM_A     0
#define SM_B     10240                 // 128 rows * 80 B
#define SM_STAGE 30720                 // + 256 rows * 80 B
#define SM_TOT   (SM_STAGE * 3)        // 92160 B

__global__ __launch_bounds__(256, 1) void gemm_mma(
        int M,
        const __half* __restrict__ A,
        const __half* __restrict__ Bh,
        const float* __restrict__ att_s, const float* __restrict__ att_d,
        float* __restrict__ as_, float* __restrict__ ad_,
        __half* __restrict__ C) {
    extern __shared__ char dsm[];
    const uint32_t sb = (uint32_t)__cvta_generic_to_shared(dsm);

    const int tid  = threadIdx.x;
    const int lane = tid & 31;
    const int warp = tid >> 5;           // 0..7
    const int wm   = warp >> 2;          // 0..1  (64 rows each)
    const int wn   = warp & 3;           // 0..3  (64 cols each)
    const int m0   = blockIdx.y * BM;
    const int n0   = blockIdx.x * BN;
    const int rowsv = min(BM, M - m0);

    float acc[4][8][4];                  // mt, nt(8 cols of 8), frag
#pragma unroll
    for (int i = 0; i < 4; i++)
#pragma unroll
        for (int j = 0; j < 8; j++)
#pragma unroll
            for (int q = 0; q < 4; q++) acc[i][j][q] = 0.f;

    const int amat = lane >> 3, ar = lane & 7;
    const int a_row_off = ((amat & 1) << 3) + ar;
    const int a_col_off = (amat >> 1) << 3;
    const int b_row_off = ((amat >> 1) << 3) + ar;
    const int b_col_off = (amat & 1) << 3;

    const int NT = DIM / 32;

    // stage one 32-K chunk: A 512 16B-chunks, B 1024 chunks
    auto stage = [&](int s, int k0) {
        const uint32_t base = sb + s * SM_STAGE;
#pragma unroll
        for (int i = tid; i < 512; i += 256) {
            const int row = i >> 2, chk = i & 3;
            const uint32_t so = (uint32_t)(row * 80 + chk * 16);
            const bool av = row < rowsv;
            const size_t ga = (size_t)(m0 + (av ? row : 0)) * DIM + k0 + chk * 8;
            cpa16(base + SM_A + so, A + ga, av ? 16 : 0);
        }
#pragma unroll
        for (int i = tid; i < 1024; i += 256) {
            const int row = i >> 2, chk = i & 3;
            const uint32_t so = (uint32_t)(row * 80 + chk * 16);
            const size_t gb = (size_t)(n0 + row) * DIM + k0 + chk * 8;
            cpa16(base + SM_B + so, Bh + gb, 16);
        }
    };

    stage(0, 0);  cpa_commit();
    stage(1, 32); cpa_commit();

    for (int it = 0; it < NT; it++) {
        cpa_wait<1>();            // buffer it%3's group complete
        __syncthreads();          // prev readers of (it+2)%3 done
        if (it + 2 < NT) { stage((it + 2) % 3, (it + 2) * 32); cpa_commit(); }

        const uint32_t bA = sb + (it % 3) * SM_STAGE;
#pragma unroll
        for (int kc = 0; kc < 2; kc++) {
            uint32_t ah[4][4];
#pragma unroll
            for (int mt = 0; mt < 4; mt++) {
                const uint32_t off =
                    (uint32_t)((wm * 64 + mt * 16 + a_row_off) * 80 +
                               (kc * 16 + a_col_off) * 2);
                ldm4(ah[mt], bA + SM_A + off);
            }
#pragma unroll
            for (int p = 0; p < 4; p++) {    // 16-col group within warp's 64
                uint32_t bh4[4];
                const uint32_t off =
                    (uint32_t)((wn * 64 + p * 16 + b_row_off) * 80 +
                               (kc * 16 + b_col_off) * 2);
                ldm4(bh4, bA + SM_B + off);
#pragma unroll
                for (int mt = 0; mt < 4; mt++)
#pragma unroll
                    for (int q = 0; q < 2; q++)
                        mma_f16(acc[mt][p * 2 + q], ah[mt], &bh4[q * 2]);
            }
        }
    }
    __syncthreads();

    // ---- epilogue: fp16 C store + fused attention dot partials (fp32) ----
    const int gr = lane >> 2, gc = (lane & 3) * 2;
#pragma unroll
    for (int mt = 0; mt < 4; mt++) {
        float s0 = 0.f, s1 = 0.f, d0 = 0.f, d1 = 0.f;
#pragma unroll
        for (int nt = 0; nt < 8; nt++) {
            const int m = m0 + wm * 64 + mt * 16 + gr;
            const int n = n0 + wn * 64 + nt * 8 + gc;
            const float2 av = *reinterpret_cast<const float2*>(att_s + n);
            const float2 dv = *reinterpret_cast<const float2*>(att_d + n);
            s0 += acc[mt][nt][0] * av.x + acc[mt][nt][1] * av.y;
            s1 += acc[mt][nt][2] * av.x + acc[mt][nt][3] * av.y;
            d0 += acc[mt][nt][0] * dv.x + acc[mt][nt][1] * dv.y;
            d1 += acc[mt][nt][2] * dv.x + acc[mt][nt][3] * dv.y;
            if (m < M) {
                __half2 c01 = __floats2half2_rn(acc[mt][nt][0], acc[mt][nt][1]);
                *reinterpret_cast<__half2*>(&C[(size_t)m * DIM + n]) = c01;
            }
            if (m + 8 < M) {
                __half2 c23 = __floats2half2_rn(acc[mt][nt][2], acc[mt][nt][3]);
                *reinterpret_cast<__half2*>(&C[(size_t)(m + 8) * DIM + n]) = c23;
            }
        }
#pragma unroll
        for (int o = 1; o < 4; o <<= 1) {
            s0 += __shfl_xor_sync(0xffffffffu, s0, o);
            s1 += __shfl_xor_sync(0xffffffffu, s1, o);
            d0 += __shfl_xor_sync(0xffffffffu, d0, o);
            d1 += __shfl_xor_sync(0xffffffffu, d1, o);
        }
        if ((lane & 3) == 0) {
            const int m = m0 + wm * 64 + mt * 16 + gr;
            if (m < M)     { atomicAdd(&as_[m], s0);     atomicAdd(&ad_[m], d0); }
            if (m + 8 < M) { atomicAdd(&as_[m + 8], s1); atomicAdd(&ad_[m + 8], d1); }
        }
    }
}

// ---------------- fp16 conversions ----------------
__global__ void split_x(const float* __restrict__ x, __half* __restrict__ hi, int total) {
    const int i = blockIdx.x * blockDim.x + threadIdx.x;
    if (i >= total) return;
    hi[i] = __float2half(x[i]);
}

// batched: z=0 -> W1, z=1 -> W2.  W [K][N] row-major -> Wt fp16 [N][K]
__global__ void split_wT(const float* __restrict__ Wa, const float* __restrict__ Wb,
                         __half* __restrict__ hA, __half* __restrict__ hB) {
    const float* W = blockIdx.z ? Wb : Wa;
    __half* hiT = blockIdx.z ? hB : hA;
    __shared__ float t[32][33];
    const int bx = blockIdx.x * 32, by = blockIdx.y * 32;
    const int tx = threadIdx.x, ty = threadIdx.y;
    #pragma unroll
    for (int j = 0; j < 4; j++)
        t[ty + j * 8][tx] = W[(size_t)(by + ty + j * 8) * DIM + bx + tx];
    __syncthreads();
    #pragma unroll
    for (int j = 0; j < 4; j++) {
        const float v = t[tx][ty + j * 8];
        hiT[(size_t)(bx + ty + j * 8) * DIM + by + tx] = __float2half(v);
    }
}

// zero cnt + both layers' attention accumulators in one launch
__global__ void zero_all(int* __restrict__ cnt,
                         float* __restrict__ a1, float* __restrict__ d1,
                         float* __restrict__ a2, float* __restrict__ d2, int n) {
    const int i = blockIdx.x * blockDim.x + threadIdx.x;
    if (i < n) { cnt[i] = 0; a1[i] = 0.f; d1[i] = 0.f; a2[i] = 0.f; d2[i] = 0.f; }
}

// ---------------- CSR build ----------------
__global__ void hist_k(const int* __restrict__ ei, int nE, int nN, int* __restrict__ cnt) {
    const int e = blockIdx.x * blockDim.x + threadIdx.x;
    if (e >= nE + nN) return;
    const int d = (e < nE) ? ei[nE + e] : (e - nE);
    atomicAdd(&cnt[d], 1);
}
__global__ void scan_rowptr(const int* __restrict__ cnt, int* __restrict__ rowptr,
                            int* __restrict__ cursor, int n) {
    __shared__ int sh[32];
    __shared__ int carry_sh;
    const int tid = threadIdx.x, lane = tid & 31, wid = tid >> 5;
    if (tid == 0) carry_sh = 0;
    __syncthreads();
    for (int base = 0; base < n; base += 1024) {
        const int i = base + tid;
        const int v = (i < n) ? cnt[i] : 0;
        int x = v;
#pragma unroll
        for (int o = 1; o < 32; o <<= 1) {
            int y = __shfl_up_sync(0xffffffffu, x, o);
            if (lane >= o) x += y;
        }
        if (lane == 31) sh[wid] = x;
        __syncthreads();
        if (wid == 0) {
            int s = sh[lane];
#pragma unroll
            for (int o = 1; o < 32; o <<= 1) {
                int y = __shfl_up_sync(0xffffffffu, s, o);
                if (lane >= o) s += y;
            }
            sh[lane] = s;
        }
        __syncthreads();
        const int incl = x + (wid > 0 ? sh[wid - 1] : 0);
        const int carry = carry_sh;
        if (i < n) { rowptr[i] = carry + incl - v; cursor[i] = carry + incl - v; }
        __syncthreads();
        if (tid == 1023) carry_sh = carry + incl;
        __syncthreads();
    }
    if (threadIdx.x == 0) rowptr[n] = carry_sh;
}
__global__ void fill_csr(const int* __restrict__ ei, int nE, int nN,
                         int* __restrict__ cursor, int* __restrict__ srcs) {
    const int e = blockIdx.x * blockDim.x + threadIdx.x;
    if (e >= nE + nN) return;
    int s, d;
    if (e < nE) { s = ei[e]; d = ei[nE + e]; }
    else        { s = d = e - nE; }
    const int pos = atomicAdd(&cursor[d], 1);
    srcs[pos] = s;
}

// ---------------- fused per-node softmax + gather (fp16 h rows) --------------
// mode 0: write float out (layer 2, no relu)
// mode 1: relu, then write fp16 (layer 1 -> layer 2 GEMM operand)
__global__ void gat_gather(const int* __restrict__ rowptr, const int* __restrict__ srcs,
                           const float* __restrict__ as_, const float* __restrict__ ad_,
                           const __half* __restrict__ h, const float* __restrict__ bias,
                           float* __restrict__ outF,
                           __half* __restrict__ outH,
                           int n, int mode) {
    const int node = blockIdx.x * (blockDim.x >> 5) + (threadIdx.x >> 5);
    const int lane = threadIdx.x & 31;
    if (node >= n) return;
    const int beg = rowptr[node], end = rowptr[node + 1];
    const float adn = ad_[node];

    float mx = -INFINITY;
    for (int j = beg + lane; j < end; j += 32) {
        float v = as_[srcs[j]] + adn;
        v = v > 0.f ? v : 0.2f * v;
        mx = fmaxf(mx, v);
    }
#pragma unroll
    for (int o = 16; o; o >>= 1) mx = fmaxf(mx, __shfl_xor_sync(0xffffffffu, mx, o));

    float den = 0.f;
    for (int j = beg + lane; j < end; j += 32) {
        float v = as_[srcs[j]] + adn;
        v = v > 0.f ? v : 0.2f * v;
        den += expf(v - mx);
    }
#pragma unroll
    for (int o = 16; o; o >>= 1) den += __shfl_xor_sync(0xffffffffu, den, o);
    const float inv = 1.f / den;

    // 3 x uint4 (8 halves each) per lane covers 768 halves per row
    float acc[3][8];
#pragma unroll
    for (int q = 0; q < 3; q++)
#pragma unroll
        for (int e8 = 0; e8 < 8; e8++) acc[q][e8] = 0.f;

    for (int j0 = beg; j0 < end; j0 += 32) {
        const int j = j0 + lane;
        float w = 0.f; int s = 0;
        if (j < end) {
            s = srcs[j];
            float v = as_[s] + adn;
            v = v > 0.f ? v : 0.2f * v;
            w = expf(v - mx) * inv;
        }
        const int cnt = min(32, end - j0);
        for (int t = 0; t < cnt; t++) {
            const float wt = __shfl_sync(0xffffffffu, w, t);
            const int   st = __shfl_sync(0xffffffffu, s, t);
            const uint4* hr = reinterpret_cast<const uint4*>(h + (size_t)st * DIM);
#pragma unroll
            for (int q = 0; q < 3; q++) {
                const uint4 v = hr[lane + 32 * q];
                const __half2* p = reinterpret_cast<const __half2*>(&v);
#pragma unroll
                for (int k = 0; k < 4; k++) {
                    const float2 f = __half22float2(p[k]);
                    acc[q][k * 2 + 0] += wt * f.x;
                    acc[q][k * 2 + 1] += wt * f.y;
                }
            }
        }
    }

#pragma unroll
    for (int q = 0; q < 3; q++) {
        const int col0 = (lane + 32 * q) * 8;
        const float4 b0 = *reinterpret_cast<const float4*>(bias + col0);
        const float4 b1 = *reinterpret_cast<const float4*>(bias + col0 + 4);
        float r[8];
        r[0] = acc[q][0] + b0.x; r[1] = acc[q][1] + b0.y;
        r[2] = acc[q][2] + b0.z; r[3] = acc[q][3] + b0.w;
        r[4] = acc[q][4] + b1.x; r[5] = acc[q][5] + b1.y;
        r[6] = acc[q][6] + b1.z; r[7] = acc[q][7] + b1.w;
        if (mode == 1) {
            __half hi8[8];
#pragma unroll
            for (int k = 0; k < 8; k++)
                hi8[k] = __float2half(fmaxf(r[k], 0.f));
            const size_t off = (size_t)node * DIM + col0;
            *reinterpret_cast<uint4*>(outH + off) = *reinterpret_cast<uint4*>(hi8);
        } else {
            float* o = outF + (size_t)node * DIM + col0;
            *reinterpret_cast<float4*>(o)     = make_float4(r[0], r[1], r[2], r[3]);
            *reinterpret_cast<float4*>(o + 4) = make_float4(r[4], r[5], r[6], r[7]);
        }
    }
}

// ---------------- launch ----------------
extern "C" void kernel_launch(void* const* d_in, const int* in_sizes, int n_in,
                              void* d_out, int out_size) {
    const float* x    = (const float*)d_in[0];
    const int*   ei   = (const int*)d_in[1];     // int32 edge_index [2, E]
    const float* W1   = (const float*)d_in[2];
    const float* as1  = (const float*)d_in[3];
    const float* ad1  = (const float*)d_in[4];
    const float* b1   = (const float*)d_in[5];
    const float* W2   = (const float*)d_in[6];
    const float* as2  = (const float*)d_in[7];
    const float* ad2  = (const float*)d_in[8];
    const float* b2   = (const float*)d_in[9];

    const int n_nodes = in_sizes[0] / DIM;
    const int n_edges = in_sizes[1] / 2;
    const int tot     = n_edges + n_nodes;

    float *asL1, *adL1, *asL2, *adL2;
    int *cnt, *rowptr, *cursor, *srcs;
    __half *hh, *ah, *w1h, *w2h;
    cudaGetSymbolAddress((void**)&hh,     g_hh);
    cudaGetSymbolAddress((void**)&asL1,   g_as1);
    cudaGetSymbolAddress((void**)&adL1,   g_ad1);
    cudaGetSymbolAddress((void**)&asL2,   g_as2);
    cudaGetSymbolAddress((void**)&adL2,   g_ad2);
    cudaGetSymbolAddress((void**)&cnt,    g_cnt);
    cudaGetSymbolAddress((void**)&rowptr, g_rowptr);
    cudaGetSymbolAddress((void**)&cursor, g_cursor);
    cudaGetSymbolAddress((void**)&srcs,   g_srcs);
    cudaGetSymbolAddress((void**)&ah,     g_ah);
    cudaGetSymbolAddress((void**)&w1h,    g_w1h);
    cudaGetSymbolAddress((void**)&w2h,    g_w2h);

    cudaFuncSetAttribute(gemm_mma, cudaFuncAttributeMaxDynamicSharedMemorySize, SM_TOT);

    const int nd_total = n_nodes * DIM;
    const dim3 gemm_grid(DIM / BN, (n_nodes + BM - 1) / BM);
    const dim3 tr_grid(DIM / 32, DIM / 32, 2), tr_blk(32, 8);

    // 0: zero everything (cnt + both layers' attention accumulators)
    zero_all<<<(n_nodes + 255) / 256, 256>>>(cnt, asL1, adL1, asL2, adL2, n_nodes);
    // 1: both weight conversions (batched, fp16)
    split_wT<<<tr_grid, tr_blk>>>(W1, W2, w1h, w2h);
    // 2: layer-1 input conversion (fp16)
    split_x<<<(nd_total + 255) / 256, 256>>>(x, ah, nd_total);
    // 3: layer-1 GEMM  <-- ncu capture slot
    gemm_mma<<<gemm_grid, 256, SM_TOT>>>(n_nodes, ah, w1h,
                                         as1, ad1, asL1, adL1, hh);
    // 4-6: CSR build (only needed by gather)
    hist_k<<<(tot + 255) / 256, 256>>>(ei, n_edges, n_nodes, cnt);
    scan_rowptr<<<1, 1024>>>(cnt, rowptr, cursor, n_nodes);
    fill_csr<<<(tot + 255) / 256, 256>>>(ei, n_edges, n_nodes, cursor, srcs);
    // 7: layer-1 gather (writes fp16 for layer 2)
    gat_gather<<<(n_nodes + 7) / 8, 256>>>(rowptr, srcs, asL1, adL1, hh, b1,
                                           nullptr, ah, n_nodes, 1);
    // 8: layer-2 GEMM
    gemm_mma<<<gemm_grid, 256, SM_TOT>>>(n_nodes, ah, w2h,
                                         as2, ad2, asL2, adL2, hh);
    // 9: layer-2 gather -> output
    gat_gather<<<(n_nodes + 7) / 8, 256>>>(rowptr, srcs, asL2, adL2, hh, b2,
                                           (float*)d_out, nullptr, n_nodes, 0);
}